// round 10
// baseline (speedup 1.0000x reference)
#include <cuda_runtime.h>
#include <cuda_bf16.h>
#include <cstdint>

#define N_NODES 100000
#define N_EDGES 600000
#define N_GRAPHS 512
#define DIM 128
#define N_LAYERS 3
#define BN_EPS 1e-5f

// ---------------- scratch (device globals; no allocation allowed) ----------
__device__ __align__(16) float g_AGG[(size_t)N_NODES * DIM];
__device__ __align__(16) float g_T[(size_t)N_NODES * DIM];
// per-layer BN accumulators (slot per layer -> no zeroing races)
__device__ float g_S1[N_LAYERS][DIM], g_Q1[N_LAYERS][DIM];
__device__ float g_S2[N_LAYERS][DIM], g_Q2[N_LAYERS][DIM];
__device__ int g_gstart[N_GRAPHS + 1];
// W fragments, interleaved {hi0,hi1,lo0,lo1}: [mat][kb 8][nb 16][lane 32][4]
__device__ __align__(16) uint32_t g_Wfrag[6 * 16384];

// ---------------- helpers ----------------------------------------------------
__device__ __forceinline__ uint32_t pack_bf16x2(float f0, float f1) {
    __nv_bfloat162 h = __floats2bfloat162_rn(f0, f1);
    return *reinterpret_cast<uint32_t*>(&h);
}
__device__ __forceinline__ void split2(float2 v, uint32_t& hi, uint32_t& lo) {
    __nv_bfloat16 h0 = __float2bfloat16_rn(v.x);
    __nv_bfloat16 h1 = __float2bfloat16_rn(v.y);
    float l0 = v.x - __bfloat162float(h0);
    float l1 = v.y - __bfloat162float(h1);
    __nv_bfloat162 hp; hp.x = h0; hp.y = h1;
    hi = *reinterpret_cast<uint32_t*>(&hp);
    lo = pack_bf16x2(l0, l1);
}
__device__ __forceinline__ void mma_bf16(float c[4], const uint32_t a[4], uint32_t b0, uint32_t b1) {
    asm volatile(
        "mma.sync.aligned.m16n8k16.row.col.f32.bf16.bf16.f32 "
        "{%0,%1,%2,%3}, {%4,%5,%6,%7}, {%8,%9}, {%0,%1,%2,%3};"
        : "+f"(c[0]), "+f"(c[1]), "+f"(c[2]), "+f"(c[3])
        : "r"(a[0]), "r"(a[1]), "r"(a[2]), "r"(a[3]), "r"(b0), "r"(b1));
}
// BN2∘BN3 folded coefficients for layer slot L (S2/Q2 must be final)
__device__ __forceinline__ void bn23_coeffs(int L, int t,
                                            const float* __restrict__ g2,
                                            const float* __restrict__ go,
                                            const float* __restrict__ bo,
                                            float& sc, float& sh) {
    const float invN = 1.0f / (float)N_NODES;
    float m = g_S2[L][t] * invN;
    float v = fmaxf(g_Q2[L][t] * invN - m * m, 0.f);
    float r2 = rsqrtf(v + BN_EPS);
    float gg = g2[t];
    float vy = gg * gg * v * r2 * r2;            // exact var of BN2 output
    float sc3 = rsqrtf(vy + BN_EPS) * go[t];
    sc = r2 * gg * sc3;
    sh = bo[t] - m * sc;
}

// ---------------- W prep: split + interleaved fragment layout ----------------
__global__ void wprep_kernel(const float* __restrict__ W1, const float* __restrict__ W2) {
    int idx = blockIdx.x * blockDim.x + threadIdx.x;   // 0 .. 6*4096-1 (frag quads)
    if (idx >= 6 * 4096) return;
    int mat = idx >> 12;
    int e = idx & 4095;
    int lane = e & 31;
    int nb = (e >> 5) & 15;
    int kb = e >> 9;
    int n = nb * 8 + (lane >> 2);
    const float* W = (mat < 3) ? (W1 + (size_t)mat * 16384)
                               : (W2 + (size_t)(mat - 3) * 16384);
    uint32_t hi0, lo0, hi1, lo1;
    {
        int k0 = kb * 16 + (lane & 3) * 2;
        split2(make_float2(W[k0 * 128 + n], W[(k0 + 1) * 128 + n]), hi0, lo0);
        int k1 = k0 + 8;
        split2(make_float2(W[k1 * 128 + n], W[(k1 + 1) * 128 + n]), hi1, lo1);
    }
    uint4 q = make_uint4(hi0, hi1, lo0, lo1);
    reinterpret_cast<uint4*>(g_Wfrag)[mat * 4096 + e] = q;
}

// ---------------- layer-0 copy: AGG = x; zero slot-0 stats -------------------
__global__ void copy_to_agg_kernel(const float* __restrict__ H) {
    if (blockIdx.x == 0 && threadIdx.x < DIM) {
        g_S1[0][threadIdx.x] = 0.f; g_Q1[0][threadIdx.x] = 0.f;
        g_S2[0][threadIdx.x] = 0.f; g_Q2[0][threadIdx.x] = 0.f;
    }
    int i = blockIdx.x * blockDim.x + threadIdx.x;
    if (i < N_NODES * (DIM / 4))
        reinterpret_cast<float4*>(g_AGG)[i] = reinterpret_cast<const float4*>(H)[i];
}

// transition copy: AGG = relu(affine(T)); zero slot-L stats (block 0)
__global__ void copy_agg_relu_kernel(int L,
                                     const float* __restrict__ g2,
                                     const float* __restrict__ go,
                                     const float* __restrict__ bo) {
    __shared__ float sc2[DIM], sh2[DIM];
    if (threadIdx.x < DIM)
        bn23_coeffs(L - 1, threadIdx.x, g2, go, bo, sc2[threadIdx.x], sh2[threadIdx.x]);
    if (blockIdx.x == 0 && threadIdx.x < DIM) {
        g_S1[L][threadIdx.x] = 0.f; g_Q1[L][threadIdx.x] = 0.f;
        g_S2[L][threadIdx.x] = 0.f; g_Q2[L][threadIdx.x] = 0.f;
    }
    __syncthreads();
    int i = blockIdx.x * blockDim.x + threadIdx.x;
    if (i >= N_NODES * (DIM / 4)) return;
    int k = (i & 31) * 4;
    float4 v = reinterpret_cast<const float4*>(g_T)[i];
    v.x = fmaxf(fmaf(v.x, sc2[k + 0], sh2[k + 0]), 0.f);
    v.y = fmaxf(fmaf(v.y, sc2[k + 1], sh2[k + 1]), 0.f);
    v.z = fmaxf(fmaf(v.z, sc2[k + 2], sh2[k + 2]), 0.f);
    v.w = fmaxf(fmaf(v.w, sc2[k + 3], sh2[k + 3]), 0.f);
    reinterpret_cast<float4*>(g_AGG)[i] = v;
}

// ---------------- scatter: AGG[dst] += f(Src[src]) ---------------------------
// TRANSFORM=0: f = identity, Src = Xin (layer 0, x)
// TRANSFORM=1: f = relu(affine(.)), Src = g_T (device-side!), coeffs slot L-1
#define SCATTER_WORK (N_EDGES * 32)          // float4 chunks total
#define SCATTER_QTR (SCATTER_WORK / 4)
template <bool TRANSFORM>
__global__ void scatter_add_kernel(const float* __restrict__ Xin,
                                   const int* __restrict__ src,
                                   const int* __restrict__ dst,
                                   int L,
                                   const float* __restrict__ g2,
                                   const float* __restrict__ go,
                                   const float* __restrict__ bo) {
    // NOTE: g_T must be resolved in DEVICE code (host shadow symbol is garbage)
    const float* Src = TRANSFORM ? (const float*)g_T : Xin;
    __shared__ float sc2[DIM], sh2[DIM];
    if (TRANSFORM) {
        if (threadIdx.x < DIM)
            bn23_coeffs(L - 1, threadIdx.x, g2, go, bo, sc2[threadIdx.x], sh2[threadIdx.x]);
        __syncthreads();
    }
    int idx = blockIdx.x * blockDim.x + threadIdx.x;
    if (idx >= SCATTER_QTR) return;
    const int j = idx & 31;
    const int k = j * 4;
    int e0 = idx >> 5;
    int e1 = (idx + SCATTER_QTR) >> 5;
    int e2 = (idx + 2 * SCATTER_QTR) >> 5;
    int e3 = (idx + 3 * SCATTER_QTR) >> 5;
    int s0 = __ldg(&src[e0]), d0 = __ldg(&dst[e0]);
    int s1 = __ldg(&src[e1]), d1 = __ldg(&dst[e1]);
    int s2 = __ldg(&src[e2]), d2 = __ldg(&dst[e2]);
    int s3 = __ldg(&src[e3]), d3 = __ldg(&dst[e3]);
    float4 v0 = reinterpret_cast<const float4*>(Src)[s0 * 32 + j];
    float4 v1 = reinterpret_cast<const float4*>(Src)[s1 * 32 + j];
    float4 v2 = reinterpret_cast<const float4*>(Src)[s2 * 32 + j];
    float4 v3 = reinterpret_cast<const float4*>(Src)[s3 * 32 + j];
    if (TRANSFORM) {
        const float c0 = sc2[k + 0], c1 = sc2[k + 1], c2 = sc2[k + 2], c3 = sc2[k + 3];
        const float h0 = sh2[k + 0], h1 = sh2[k + 1], h2 = sh2[k + 2], h3 = sh2[k + 3];
        v0.x = fmaxf(fmaf(v0.x, c0, h0), 0.f); v0.y = fmaxf(fmaf(v0.y, c1, h1), 0.f);
        v0.z = fmaxf(fmaf(v0.z, c2, h2), 0.f); v0.w = fmaxf(fmaf(v0.w, c3, h3), 0.f);
        v1.x = fmaxf(fmaf(v1.x, c0, h0), 0.f); v1.y = fmaxf(fmaf(v1.y, c1, h1), 0.f);
        v1.z = fmaxf(fmaf(v1.z, c2, h2), 0.f); v1.w = fmaxf(fmaf(v1.w, c3, h3), 0.f);
        v2.x = fmaxf(fmaf(v2.x, c0, h0), 0.f); v2.y = fmaxf(fmaf(v2.y, c1, h1), 0.f);
        v2.z = fmaxf(fmaf(v2.z, c2, h2), 0.f); v2.w = fmaxf(fmaf(v2.w, c3, h3), 0.f);
        v3.x = fmaxf(fmaf(v3.x, c0, h0), 0.f); v3.y = fmaxf(fmaf(v3.y, c1, h1), 0.f);
        v3.z = fmaxf(fmaf(v3.z, c2, h2), 0.f); v3.w = fmaxf(fmaf(v3.w, c3, h3), 0.f);
    }
    atomicAdd(reinterpret_cast<float4*>(g_AGG) + d0 * 32 + j, v0);
    atomicAdd(reinterpret_cast<float4*>(g_AGG) + d1 * 32 + j, v1);
    atomicAdd(reinterpret_cast<float4*>(g_AGG) + d2 * 32 + j, v2);
    atomicAdd(reinterpret_cast<float4*>(g_AGG) + d3 * 32 + j, v3);
}

// ---------------- HMMA GEMM + column stats -----------------------------------
// PHASE 1: T = AGG @ W + b       (stats -> S1[L]/Q1[L])
// PHASE 2: T = BN1(T) @ W + b    (in-place; BN1 from S1[L]; stats -> S2[L]/Q2[L])
// In-place safety: each warp reads/writes only its own 16 rows; all loads
// precede stores in program order (mma.sync converges the warp).
#define SMB_BFRAG 0
#define SMB_BIAS 65536
#define SMB_SCL 66048
#define SMB_SHF 66560
#define SMB_SS 67072
#define SMB_SQ 67584
#define SMB_TOTAL 68096

template <int PHASE>
__global__ void __launch_bounds__(256) gemm_mma_kernel(int mat, int L,
                                                       const float* __restrict__ bias,
                                                       const float* __restrict__ bn_g,
                                                       const float* __restrict__ bn_b) {
    const float* A   = (PHASE == 1) ? g_AGG : g_T;
    float*       Out = g_T;
    float*       Sg  = (PHASE == 1) ? g_S1[L] : g_S2[L];
    float*       Qg  = (PHASE == 1) ? g_Q1[L] : g_Q2[L];

    extern __shared__ __align__(16) char smem[];
    uint32_t* sBf  = reinterpret_cast<uint32_t*>(smem + SMB_BFRAG);
    float* sBias = reinterpret_cast<float*>(smem + SMB_BIAS);
    float* sScl  = reinterpret_cast<float*>(smem + SMB_SCL);
    float* sShf  = reinterpret_cast<float*>(smem + SMB_SHF);
    float* sS    = reinterpret_cast<float*>(smem + SMB_SS);
    float* sQ    = reinterpret_cast<float*>(smem + SMB_SQ);

    const int tid = threadIdx.x;
    const int wid = tid >> 5;
    const int lane = tid & 31;
    const int qrow = lane >> 2;
    const int qk = (lane & 3) * 2;
    const int row0 = blockIdx.x * 128;

    {
        const uint4* wf = reinterpret_cast<const uint4*>(g_Wfrag + mat * 16384);
        uint4* bf = reinterpret_cast<uint4*>(sBf);
#pragma unroll
        for (int i = 0; i < 16; i++) {
            int idx = tid + i * 256;
            bf[idx] = wf[idx];
        }
    }
    if (tid < DIM) {
        sBias[tid] = bias[tid];
        sS[tid] = 0.f; sQ[tid] = 0.f;
        if (PHASE == 2) {
            const float invN = 1.0f / (float)N_NODES;
            float m = g_S1[L][tid] * invN;
            float v = fmaxf(g_Q1[L][tid] * invN - m * m, 0.f);
            float sc = rsqrtf(v + BN_EPS) * bn_g[tid];
            sScl[tid] = sc;
            sShf[tid] = bn_b[tid] - m * sc;
        }
    }
    __syncthreads();

    const int r0 = row0 + wid * 16 + qrow;
    const int r1 = r0 + 8;
    const bool v0 = (r0 < N_NODES);
    const bool v1 = (r1 < N_NODES);
    const float* a0p = A + (size_t)r0 * DIM;
    const float* a1p = A + (size_t)r1 * DIM;

    float c[16][4];
#pragma unroll
    for (int nb = 0; nb < 16; nb++) {
        c[nb][0] = 0.f; c[nb][1] = 0.f; c[nb][2] = 0.f; c[nb][3] = 0.f;
    }

#pragma unroll
    for (int kb = 0; kb < 8; kb++) {
        const int c0 = kb * 16 + qk;
        float2 x00 = make_float2(0.f, 0.f), x01 = x00, x10 = x00, x11 = x00;
        if (v0) {
            x00 = *reinterpret_cast<const float2*>(a0p + c0);
            x01 = *reinterpret_cast<const float2*>(a0p + c0 + 8);
        }
        if (v1) {
            x10 = *reinterpret_cast<const float2*>(a1p + c0);
            x11 = *reinterpret_cast<const float2*>(a1p + c0 + 8);
        }
        if (PHASE == 2) {
            x00.x = fmaf(x00.x, sScl[c0], sShf[c0]);
            x00.y = fmaf(x00.y, sScl[c0 + 1], sShf[c0 + 1]);
            x01.x = fmaf(x01.x, sScl[c0 + 8], sShf[c0 + 8]);
            x01.y = fmaf(x01.y, sScl[c0 + 9], sShf[c0 + 9]);
            x10.x = fmaf(x10.x, sScl[c0], sShf[c0]);
            x10.y = fmaf(x10.y, sScl[c0 + 1], sShf[c0 + 1]);
            x11.x = fmaf(x11.x, sScl[c0 + 8], sShf[c0 + 8]);
            x11.y = fmaf(x11.y, sScl[c0 + 9], sShf[c0 + 9]);
        }
        uint32_t ahi[4], alo[4];
        split2(x00, ahi[0], alo[0]);
        split2(x10, ahi[1], alo[1]);
        split2(x01, ahi[2], alo[2]);
        split2(x11, ahi[3], alo[3]);

#pragma unroll
        for (int nb = 0; nb < 16; nb++) {
            const uint4 b = *reinterpret_cast<const uint4*>(&sBf[((kb * 16 + nb) * 32 + lane) * 4]);
            mma_bf16(c[nb], ahi, b.x, b.y);
            mma_bf16(c[nb], ahi, b.z, b.w);
            mma_bf16(c[nb], alo, b.x, b.y);
        }
    }

    // ---- epilogue: bias + store + column stats ----
#pragma unroll
    for (int nb = 0; nb < 16; nb++) {
        const int cn = nb * 8 + qk;
        const float b0 = sBias[cn], b1 = sBias[cn + 1];
        float o00 = v0 ? (c[nb][0] + b0) : 0.f;
        float o01 = v0 ? (c[nb][1] + b1) : 0.f;
        float o10 = v1 ? (c[nb][2] + b0) : 0.f;
        float o11 = v1 ? (c[nb][3] + b1) : 0.f;
        if (v0) *reinterpret_cast<float2*>(Out + (size_t)r0 * DIM + cn) = make_float2(o00, o01);
        if (v1) *reinterpret_cast<float2*>(Out + (size_t)r1 * DIM + cn) = make_float2(o10, o11);
        float s0 = o00 + o10, s1 = o01 + o11;
        float q0 = o00 * o00 + o10 * o10, q1 = o01 * o01 + o11 * o11;
#pragma unroll
        for (int off = 4; off < 32; off <<= 1) {
            s0 += __shfl_down_sync(0xFFFFFFFF, s0, off);
            s1 += __shfl_down_sync(0xFFFFFFFF, s1, off);
            q0 += __shfl_down_sync(0xFFFFFFFF, q0, off);
            q1 += __shfl_down_sync(0xFFFFFFFF, q1, off);
        }
        if (lane < 4) {
            atomicAdd(&sS[cn], s0);
            atomicAdd(&sS[cn + 1], s1);
            atomicAdd(&sQ[cn], q0);
            atomicAdd(&sQ[cn + 1], q1);
        }
    }
    __syncthreads();
    if (tid < DIM) { atomicAdd(&Sg[tid], sS[tid]); atomicAdd(&Qg[tid], sQ[tid]); }
}

// final layer: Hout = relu(affine(T))
__global__ void relu_out_kernel(float* __restrict__ H, int L,
                                const float* __restrict__ g2,
                                const float* __restrict__ go,
                                const float* __restrict__ bo) {
    __shared__ float sc2[DIM], sh2[DIM];
    if (threadIdx.x < DIM)
        bn23_coeffs(L, threadIdx.x, g2, go, bo, sc2[threadIdx.x], sh2[threadIdx.x]);
    __syncthreads();
    int i = blockIdx.x * blockDim.x + threadIdx.x;
    if (i >= N_NODES * (DIM / 4)) return;
    int k = (i & 31) * 4;
    float4 v = reinterpret_cast<const float4*>(g_T)[i];
    v.x = fmaxf(fmaf(v.x, sc2[k + 0], sh2[k + 0]), 0.f);
    v.y = fmaxf(fmaf(v.y, sc2[k + 1], sh2[k + 1]), 0.f);
    v.z = fmaxf(fmaf(v.z, sc2[k + 2], sh2[k + 2]), 0.f);
    v.w = fmaxf(fmaf(v.w, sc2[k + 3], sh2[k + 3]), 0.f);
    reinterpret_cast<float4*>(H)[i] = v;
}

// ---------------- pooling + classifier ---------------------------------------
__global__ void seg_bounds_kernel(const int* __restrict__ batch) {
    int n = blockIdx.x * blockDim.x + threadIdx.x;
    if (n > N_NODES) return;
    int prev = (n == 0) ? -1 : batch[n - 1];
    int cur = (n == N_NODES) ? N_GRAPHS : batch[n];
    for (int g = prev + 1; g <= cur; g++) g_gstart[g] = n;
}

__global__ void graph_fc_kernel(const float* __restrict__ H,
                                const float* __restrict__ fcW,
                                const float* __restrict__ fcb,
                                float* __restrict__ Gout,
                                float* __restrict__ Cout) {
    int g = blockIdx.x;
    int t = threadIdx.x;
    int beg = g_gstart[g], end = g_gstart[g + 1];
    float s = 0.f;
    for (int r = beg; r < end; r++) s += H[r * DIM + t];
    float cnt = fmaxf((float)(end - beg), 1.0f);
    float ge = s / cnt;
    Gout[g * DIM + t] = ge;
    __shared__ float r0[DIM], r1[DIM];
    r0[t] = ge * fcW[t * 2 + 0];
    r1[t] = ge * fcW[t * 2 + 1];
    __syncthreads();
    for (int sh = 64; sh > 0; sh >>= 1) {
        if (t < sh) { r0[t] += r0[t + sh]; r1[t] += r1[t + sh]; }
        __syncthreads();
    }
    if (t == 0) {
        Cout[g * 2 + 0] = r0[0] + fcb[0];
        Cout[g * 2 + 1] = r1[0] + fcb[1];
    }
}

// ---------------- launcher ---------------------------------------------------
extern "C" void kernel_launch(void* const* d_in, const int* in_sizes, int n_in,
                              void* d_out, int out_size) {
    const float* x     = (const float*)d_in[0];
    const int*   ei    = (const int*)d_in[1];
    const int*   batch = (const int*)d_in[2];
    const float* W1    = (const float*)d_in[3];
    const float* b1    = (const float*)d_in[4];
    const float* g1    = (const float*)d_in[5];
    const float* bt1   = (const float*)d_in[6];
    const float* W2    = (const float*)d_in[7];
    const float* b2    = (const float*)d_in[8];
    const float* g2    = (const float*)d_in[9];
    // d_in[10] (bt2) cancels analytically in BN2∘BN3
    const float* go    = (const float*)d_in[11];
    const float* bo    = (const float*)d_in[12];
    const float* fcW   = (const float*)d_in[13];
    const float* fcb   = (const float*)d_in[14];

    float* out  = (float*)d_out;
    float* Hout = out;
    float* Gout = out + (size_t)N_NODES * DIM;
    float* Cout = Gout + (size_t)N_GRAPHS * DIM;

    const int* src = ei;
    const int* dst = ei + N_EDGES;

    static bool attr_set = false;
    if (!attr_set) {
        cudaFuncSetAttribute(gemm_mma_kernel<1>, cudaFuncAttributeMaxDynamicSharedMemorySize, SMB_TOTAL);
        cudaFuncSetAttribute(gemm_mma_kernel<2>, cudaFuncAttributeMaxDynamicSharedMemorySize, SMB_TOTAL);
        attr_set = true;
    }

    const int nCopyBlocks    = (N_NODES * (DIM / 4)) / 256;      // 12500
    const int nScatterBlocks = (SCATTER_QTR + 255) / 256;        // 18750
    const int nGemmBlocks    = (N_NODES + 127) / 128;            // 782

    wprep_kernel<<<(6 * 4096 + 255) / 256, 256>>>(W1, W2);
    seg_bounds_kernel<<<(N_NODES + 256) / 256, 256>>>(batch);

    for (int i = 0; i < N_LAYERS; i++) {
        if (i == 0) {
            copy_to_agg_kernel<<<nCopyBlocks, 256>>>(x);
            scatter_add_kernel<false><<<nScatterBlocks, 256>>>(x, src, dst, 0,
                                                               nullptr, nullptr, nullptr);
        } else {
            copy_agg_relu_kernel<<<nCopyBlocks, 256>>>(i, g2 + (i - 1) * DIM,
                                                       go + (i - 1) * DIM, bo + (i - 1) * DIM);
            scatter_add_kernel<true><<<nScatterBlocks, 256>>>(nullptr, src, dst, i,
                                                              g2 + (i - 1) * DIM,
                                                              go + (i - 1) * DIM,
                                                              bo + (i - 1) * DIM);
        }
        gemm_mma_kernel<1><<<nGemmBlocks, 256, SMB_TOTAL>>>(i, i, b1 + i * DIM,
                                                            nullptr, nullptr);
        gemm_mma_kernel<2><<<nGemmBlocks, 256, SMB_TOTAL>>>(i + 3, i, b2 + i * DIM,
                                                            g1 + i * DIM, bt1 + i * DIM);
    }

    relu_out_kernel<<<nCopyBlocks, 256>>>(Hout, N_LAYERS - 1,
                                          g2 + (N_LAYERS - 1) * DIM,
                                          go + (N_LAYERS - 1) * DIM,
                                          bo + (N_LAYERS - 1) * DIM);
    graph_fc_kernel<<<N_GRAPHS, 128>>>(Hout, fcW, fcb, Gout, Cout);
}

// round 11
// speedup vs baseline: 1.0005x; 1.0005x over previous
#include <cuda_runtime.h>
#include <cuda_bf16.h>
#include <cstdint>

#define N_NODES 100000
#define N_EDGES 600000
#define N_GRAPHS 512
#define DIM 128
#define N_LAYERS 3
#define BN_EPS 1e-5f

// ---------------- scratch (device globals; no allocation allowed) ----------
__device__ __align__(16) float g_AGG[(size_t)N_NODES * DIM];
__device__ __align__(16) float g_T[(size_t)N_NODES * DIM];
// per-layer BN accumulators (slot per layer -> no zeroing races)
__device__ float g_S1[N_LAYERS][DIM], g_Q1[N_LAYERS][DIM];
__device__ float g_S2[N_LAYERS][DIM], g_Q2[N_LAYERS][DIM];
__device__ int g_gstart[N_GRAPHS + 1];
// W fragments, interleaved {hi0,hi1,lo0,lo1}: [mat][kb 8][nb 16][lane 32][4]
__device__ __align__(16) uint32_t g_Wfrag[6 * 16384];

// ---------------- helpers ----------------------------------------------------
__device__ __forceinline__ uint32_t pack_bf16x2(float f0, float f1) {
    __nv_bfloat162 h = __floats2bfloat162_rn(f0, f1);
    return *reinterpret_cast<uint32_t*>(&h);
}
__device__ __forceinline__ void split2(float2 v, uint32_t& hi, uint32_t& lo) {
    __nv_bfloat16 h0 = __float2bfloat16_rn(v.x);
    __nv_bfloat16 h1 = __float2bfloat16_rn(v.y);
    float l0 = v.x - __bfloat162float(h0);
    float l1 = v.y - __bfloat162float(h1);
    __nv_bfloat162 hp; hp.x = h0; hp.y = h1;
    hi = *reinterpret_cast<uint32_t*>(&hp);
    lo = pack_bf16x2(l0, l1);
}
__device__ __forceinline__ void mma_bf16(float c[4], const uint32_t a[4], uint32_t b0, uint32_t b1) {
    asm volatile(
        "mma.sync.aligned.m16n8k16.row.col.f32.bf16.bf16.f32 "
        "{%0,%1,%2,%3}, {%4,%5,%6,%7}, {%8,%9}, {%0,%1,%2,%3};"
        : "+f"(c[0]), "+f"(c[1]), "+f"(c[2]), "+f"(c[3])
        : "r"(a[0]), "r"(a[1]), "r"(a[2]), "r"(a[3]), "r"(b0), "r"(b1));
}
// BN2∘BN3 folded coefficients for layer slot L (S2/Q2 must be final)
__device__ __forceinline__ void bn23_coeffs(int L, int t,
                                            const float* __restrict__ g2,
                                            const float* __restrict__ go,
                                            const float* __restrict__ bo,
                                            float& sc, float& sh) {
    const float invN = 1.0f / (float)N_NODES;
    float m = g_S2[L][t] * invN;
    float v = fmaxf(g_Q2[L][t] * invN - m * m, 0.f);
    float r2 = rsqrtf(v + BN_EPS);
    float gg = g2[t];
    float vy = gg * gg * v * r2 * r2;            // exact var of BN2 output
    float sc3 = rsqrtf(vy + BN_EPS) * go[t];
    sc = r2 * gg * sc3;
    sh = bo[t] - m * sc;
}

// ---------------- prep: W split/layout + graph segment bounds ----------------
__global__ void prep_kernel(const float* __restrict__ W1, const float* __restrict__ W2,
                            const int* __restrict__ batch) {
    int idx = blockIdx.x * blockDim.x + threadIdx.x;
    // part 1: W fragments (6*4096 quads)
    if (idx < 6 * 4096) {
        int mat = idx >> 12;
        int e = idx & 4095;
        int lane = e & 31;
        int nb = (e >> 5) & 15;
        int kb = e >> 9;
        int n = nb * 8 + (lane >> 2);
        const float* W = (mat < 3) ? (W1 + (size_t)mat * 16384)
                                   : (W2 + (size_t)(mat - 3) * 16384);
        uint32_t hi0, lo0, hi1, lo1;
        int k0 = kb * 16 + (lane & 3) * 2;
        split2(make_float2(W[k0 * 128 + n], W[(k0 + 1) * 128 + n]), hi0, lo0);
        int k1 = k0 + 8;
        split2(make_float2(W[k1 * 128 + n], W[(k1 + 1) * 128 + n]), hi1, lo1);
        reinterpret_cast<uint4*>(g_Wfrag)[mat * 4096 + e] = make_uint4(hi0, hi1, lo0, lo1);
    }
    // part 2: segment bounds for sorted batch
    if (idx <= N_NODES) {
        int prev = (idx == 0) ? -1 : batch[idx - 1];
        int cur = (idx == N_NODES) ? N_GRAPHS : batch[idx];
        for (int g = prev + 1; g <= cur; g++) g_gstart[g] = idx;
    }
}

// ---------------- layer-0 copy: AGG = x; zero slot-0 stats -------------------
__global__ void copy_to_agg_kernel(const float* __restrict__ H) {
    if (blockIdx.x == 0 && threadIdx.x < DIM) {
        g_S1[0][threadIdx.x] = 0.f; g_Q1[0][threadIdx.x] = 0.f;
        g_S2[0][threadIdx.x] = 0.f; g_Q2[0][threadIdx.x] = 0.f;
    }
    int i = blockIdx.x * blockDim.x + threadIdx.x;
    if (i < N_NODES * (DIM / 4))
        reinterpret_cast<float4*>(g_AGG)[i] = reinterpret_cast<const float4*>(H)[i];
}

// transition copy: AGG = relu(affine(T)); zero slot-L stats (block 0)
__global__ void copy_agg_relu_kernel(int L,
                                     const float* __restrict__ g2,
                                     const float* __restrict__ go,
                                     const float* __restrict__ bo) {
    __shared__ float sc2[DIM], sh2[DIM];
    if (threadIdx.x < DIM)
        bn23_coeffs(L - 1, threadIdx.x, g2, go, bo, sc2[threadIdx.x], sh2[threadIdx.x]);
    if (blockIdx.x == 0 && threadIdx.x < DIM) {
        g_S1[L][threadIdx.x] = 0.f; g_Q1[L][threadIdx.x] = 0.f;
        g_S2[L][threadIdx.x] = 0.f; g_Q2[L][threadIdx.x] = 0.f;
    }
    __syncthreads();
    int i = blockIdx.x * blockDim.x + threadIdx.x;
    if (i >= N_NODES * (DIM / 4)) return;
    int k = (i & 31) * 4;
    float4 v = reinterpret_cast<const float4*>(g_T)[i];
    v.x = fmaxf(fmaf(v.x, sc2[k + 0], sh2[k + 0]), 0.f);
    v.y = fmaxf(fmaf(v.y, sc2[k + 1], sh2[k + 1]), 0.f);
    v.z = fmaxf(fmaf(v.z, sc2[k + 2], sh2[k + 2]), 0.f);
    v.w = fmaxf(fmaf(v.w, sc2[k + 3], sh2[k + 3]), 0.f);
    reinterpret_cast<float4*>(g_AGG)[i] = v;
}

// ---------------- scatter: AGG[dst] += f(Src[src]) ---------------------------
// TRANSFORM=0: f = identity, Src = Xin (layer 0, x)
// TRANSFORM=1: f = relu(affine(.)), Src = g_T (device-side!), coeffs slot L-1
#define SCATTER_WORK (N_EDGES * 32)          // float4 chunks total
#define SCATTER_QTR (SCATTER_WORK / 4)
template <bool TRANSFORM>
__global__ void scatter_add_kernel(const float* __restrict__ Xin,
                                   const int* __restrict__ src,
                                   const int* __restrict__ dst,
                                   int L,
                                   const float* __restrict__ g2,
                                   const float* __restrict__ go,
                                   const float* __restrict__ bo) {
    const float* Src = TRANSFORM ? (const float*)g_T : Xin;
    __shared__ float sc2[DIM], sh2[DIM];
    if (TRANSFORM) {
        if (threadIdx.x < DIM)
            bn23_coeffs(L - 1, threadIdx.x, g2, go, bo, sc2[threadIdx.x], sh2[threadIdx.x]);
        __syncthreads();
    }
    int idx = blockIdx.x * blockDim.x + threadIdx.x;
    if (idx >= SCATTER_QTR) return;
    const int j = idx & 31;
    const int k = j * 4;
    int e0 = idx >> 5;
    int e1 = (idx + SCATTER_QTR) >> 5;
    int e2 = (idx + 2 * SCATTER_QTR) >> 5;
    int e3 = (idx + 3 * SCATTER_QTR) >> 5;
    int s0 = __ldg(&src[e0]), d0 = __ldg(&dst[e0]);
    int s1 = __ldg(&src[e1]), d1 = __ldg(&dst[e1]);
    int s2 = __ldg(&src[e2]), d2 = __ldg(&dst[e2]);
    int s3 = __ldg(&src[e3]), d3 = __ldg(&dst[e3]);
    float4 v0 = reinterpret_cast<const float4*>(Src)[s0 * 32 + j];
    float4 v1 = reinterpret_cast<const float4*>(Src)[s1 * 32 + j];
    float4 v2 = reinterpret_cast<const float4*>(Src)[s2 * 32 + j];
    float4 v3 = reinterpret_cast<const float4*>(Src)[s3 * 32 + j];
    if (TRANSFORM) {
        const float c0 = sc2[k + 0], c1 = sc2[k + 1], c2 = sc2[k + 2], c3 = sc2[k + 3];
        const float h0 = sh2[k + 0], h1 = sh2[k + 1], h2 = sh2[k + 2], h3 = sh2[k + 3];
        v0.x = fmaxf(fmaf(v0.x, c0, h0), 0.f); v0.y = fmaxf(fmaf(v0.y, c1, h1), 0.f);
        v0.z = fmaxf(fmaf(v0.z, c2, h2), 0.f); v0.w = fmaxf(fmaf(v0.w, c3, h3), 0.f);
        v1.x = fmaxf(fmaf(v1.x, c0, h0), 0.f); v1.y = fmaxf(fmaf(v1.y, c1, h1), 0.f);
        v1.z = fmaxf(fmaf(v1.z, c2, h2), 0.f); v1.w = fmaxf(fmaf(v1.w, c3, h3), 0.f);
        v2.x = fmaxf(fmaf(v2.x, c0, h0), 0.f); v2.y = fmaxf(fmaf(v2.y, c1, h1), 0.f);
        v2.z = fmaxf(fmaf(v2.z, c2, h2), 0.f); v2.w = fmaxf(fmaf(v2.w, c3, h3), 0.f);
        v3.x = fmaxf(fmaf(v3.x, c0, h0), 0.f); v3.y = fmaxf(fmaf(v3.y, c1, h1), 0.f);
        v3.z = fmaxf(fmaf(v3.z, c2, h2), 0.f); v3.w = fmaxf(fmaf(v3.w, c3, h3), 0.f);
    }
    atomicAdd(reinterpret_cast<float4*>(g_AGG) + d0 * 32 + j, v0);
    atomicAdd(reinterpret_cast<float4*>(g_AGG) + d1 * 32 + j, v1);
    atomicAdd(reinterpret_cast<float4*>(g_AGG) + d2 * 32 + j, v2);
    atomicAdd(reinterpret_cast<float4*>(g_AGG) + d3 * 32 + j, v3);
}

// ---------------- HMMA GEMM + column stats -----------------------------------
// PHASE 1: T = AGG @ W + b       (stats -> S1[L]/Q1[L])
// PHASE 2: T = BN1(T) @ W + b    (in-place; BN1 from S1[L]; stats -> S2[L]/Q2[L])
#define SMB_BFRAG 0
#define SMB_BIAS 65536
#define SMB_SCL 66048
#define SMB_SHF 66560
#define SMB_SS 67072
#define SMB_SQ 67584
#define SMB_TOTAL 68096

template <int PHASE>
__global__ void __launch_bounds__(256) gemm_mma_kernel(int mat, int L,
                                                       const float* __restrict__ bias,
                                                       const float* __restrict__ bn_g,
                                                       const float* __restrict__ bn_b) {
    const float* A   = (PHASE == 1) ? g_AGG : g_T;
    float*       Out = g_T;
    float*       Sg  = (PHASE == 1) ? g_S1[L] : g_S2[L];
    float*       Qg  = (PHASE == 1) ? g_Q1[L] : g_Q2[L];

    extern __shared__ __align__(16) char smem[];
    uint32_t* sBf  = reinterpret_cast<uint32_t*>(smem + SMB_BFRAG);
    float* sBias = reinterpret_cast<float*>(smem + SMB_BIAS);
    float* sScl  = reinterpret_cast<float*>(smem + SMB_SCL);
    float* sShf  = reinterpret_cast<float*>(smem + SMB_SHF);
    float* sS    = reinterpret_cast<float*>(smem + SMB_SS);
    float* sQ    = reinterpret_cast<float*>(smem + SMB_SQ);

    const int tid = threadIdx.x;
    const int wid = tid >> 5;
    const int lane = tid & 31;
    const int qrow = lane >> 2;
    const int qk = (lane & 3) * 2;
    const int row0 = blockIdx.x * 128;

    {
        const uint4* wf = reinterpret_cast<const uint4*>(g_Wfrag + mat * 16384);
        uint4* bf = reinterpret_cast<uint4*>(sBf);
#pragma unroll
        for (int i = 0; i < 16; i++) {
            int idx = tid + i * 256;
            bf[idx] = wf[idx];
        }
    }
    if (tid < DIM) {
        sBias[tid] = bias[tid];
        sS[tid] = 0.f; sQ[tid] = 0.f;
        if (PHASE == 2) {
            const float invN = 1.0f / (float)N_NODES;
            float m = g_S1[L][tid] * invN;
            float v = fmaxf(g_Q1[L][tid] * invN - m * m, 0.f);
            float sc = rsqrtf(v + BN_EPS) * bn_g[tid];
            sScl[tid] = sc;
            sShf[tid] = bn_b[tid] - m * sc;
        }
    }
    __syncthreads();

    const int r0 = row0 + wid * 16 + qrow;
    const int r1 = r0 + 8;
    const bool v0 = (r0 < N_NODES);
    const bool v1 = (r1 < N_NODES);
    const float* a0p = A + (size_t)r0 * DIM;
    const float* a1p = A + (size_t)r1 * DIM;

    float c[16][4];
#pragma unroll
    for (int nb = 0; nb < 16; nb++) {
        c[nb][0] = 0.f; c[nb][1] = 0.f; c[nb][2] = 0.f; c[nb][3] = 0.f;
    }

#pragma unroll
    for (int kb = 0; kb < 8; kb++) {
        const int c0 = kb * 16 + qk;
        float2 x00 = make_float2(0.f, 0.f), x01 = x00, x10 = x00, x11 = x00;
        if (v0) {
            x00 = *reinterpret_cast<const float2*>(a0p + c0);
            x01 = *reinterpret_cast<const float2*>(a0p + c0 + 8);
        }
        if (v1) {
            x10 = *reinterpret_cast<const float2*>(a1p + c0);
            x11 = *reinterpret_cast<const float2*>(a1p + c0 + 8);
        }
        if (PHASE == 2) {
            x00.x = fmaf(x00.x, sScl[c0], sShf[c0]);
            x00.y = fmaf(x00.y, sScl[c0 + 1], sShf[c0 + 1]);
            x01.x = fmaf(x01.x, sScl[c0 + 8], sShf[c0 + 8]);
            x01.y = fmaf(x01.y, sScl[c0 + 9], sShf[c0 + 9]);
            x10.x = fmaf(x10.x, sScl[c0], sShf[c0]);
            x10.y = fmaf(x10.y, sScl[c0 + 1], sShf[c0 + 1]);
            x11.x = fmaf(x11.x, sScl[c0 + 8], sShf[c0 + 8]);
            x11.y = fmaf(x11.y, sScl[c0 + 9], sShf[c0 + 9]);
        }
        uint32_t ahi[4], alo[4];
        split2(x00, ahi[0], alo[0]);
        split2(x10, ahi[1], alo[1]);
        split2(x01, ahi[2], alo[2]);
        split2(x11, ahi[3], alo[3]);

#pragma unroll
        for (int nb = 0; nb < 16; nb++) {
            const uint4 b = *reinterpret_cast<const uint4*>(&sBf[((kb * 16 + nb) * 32 + lane) * 4]);
            mma_bf16(c[nb], ahi, b.x, b.y);
            mma_bf16(c[nb], ahi, b.z, b.w);
            mma_bf16(c[nb], alo, b.x, b.y);
        }
    }

    // ---- epilogue: bias + store + column stats ----
#pragma unroll
    for (int nb = 0; nb < 16; nb++) {
        const int cn = nb * 8 + qk;
        const float b0 = sBias[cn], b1 = sBias[cn + 1];
        float o00 = v0 ? (c[nb][0] + b0) : 0.f;
        float o01 = v0 ? (c[nb][1] + b1) : 0.f;
        float o10 = v1 ? (c[nb][2] + b0) : 0.f;
        float o11 = v1 ? (c[nb][3] + b1) : 0.f;
        if (v0) *reinterpret_cast<float2*>(Out + (size_t)r0 * DIM + cn) = make_float2(o00, o01);
        if (v1) *reinterpret_cast<float2*>(Out + (size_t)r1 * DIM + cn) = make_float2(o10, o11);
        float s0 = o00 + o10, s1 = o01 + o11;
        float q0 = o00 * o00 + o10 * o10, q1 = o01 * o01 + o11 * o11;
#pragma unroll
        for (int off = 4; off < 32; off <<= 1) {
            s0 += __shfl_down_sync(0xFFFFFFFF, s0, off);
            s1 += __shfl_down_sync(0xFFFFFFFF, s1, off);
            q0 += __shfl_down_sync(0xFFFFFFFF, q0, off);
            q1 += __shfl_down_sync(0xFFFFFFFF, q1, off);
        }
        if (lane < 4) {
            atomicAdd(&sS[cn], s0);
            atomicAdd(&sS[cn + 1], s1);
            atomicAdd(&sQ[cn], q0);
            atomicAdd(&sQ[cn + 1], q1);
        }
    }
    __syncthreads();
    if (tid < DIM) { atomicAdd(&Sg[tid], sS[tid]); atomicAdd(&Qg[tid], sQ[tid]); }
}

// ---------------- fused final transform + per-graph pooling ------------------
// grid (N_GRAPHS, 4); block (g, cb) handles cols [cb*32, cb*32+32).
// Reads T, applies BN2∘BN3 + ReLU, writes node embeddings + Gout columns.
__global__ void pool_transform_kernel(float* __restrict__ H,
                                      float* __restrict__ Gout,
                                      int L,
                                      const float* __restrict__ g2,
                                      const float* __restrict__ go,
                                      const float* __restrict__ bo) {
    const int g = blockIdx.x;
    const int cb = blockIdx.y;
    const int tc = threadIdx.x & 31;    // column within group
    const int ty = threadIdx.x >> 5;    // row phase 0..3
    const int col = cb * 32 + tc;

    __shared__ float sc2[32], sh2[32];
    __shared__ float part[4][32];
    if (threadIdx.x < 32)
        bn23_coeffs(L, col - tc + threadIdx.x, g2, go, bo, sc2[threadIdx.x], sh2[threadIdx.x]);
    __syncthreads();

    const int beg = g_gstart[g], end = g_gstart[g + 1];
    const float sc = sc2[tc], sh = sh2[tc];
    float sum = 0.f;
    for (int r = beg + ty; r < end; r += 4) {
        float v = g_T[(size_t)r * DIM + col];
        v = fmaxf(fmaf(v, sc, sh), 0.f);
        H[(size_t)r * DIM + col] = v;
        sum += v;
    }
    part[ty][tc] = sum;
    __syncthreads();
    if (ty == 0) {
        float tot = part[0][tc] + part[1][tc] + part[2][tc] + part[3][tc];
        float cnt = fmaxf((float)(end - beg), 1.0f);
        Gout[g * DIM + col] = tot / cnt;
    }
}

// classifier over graph embeddings
__global__ void fc_kernel(const float* __restrict__ Gout,
                          const float* __restrict__ fcW,
                          const float* __restrict__ fcb,
                          float* __restrict__ Cout) {
    int g = blockIdx.x;
    int t = threadIdx.x;   // 128
    float ge = Gout[g * DIM + t];
    __shared__ float r0[DIM], r1[DIM];
    r0[t] = ge * fcW[t * 2 + 0];
    r1[t] = ge * fcW[t * 2 + 1];
    __syncthreads();
    for (int sh = 64; sh > 0; sh >>= 1) {
        if (t < sh) { r0[t] += r0[t + sh]; r1[t] += r1[t + sh]; }
        __syncthreads();
    }
    if (t == 0) {
        Cout[g * 2 + 0] = r0[0] + fcb[0];
        Cout[g * 2 + 1] = r1[0] + fcb[1];
    }
}

// ---------------- launcher ---------------------------------------------------
extern "C" void kernel_launch(void* const* d_in, const int* in_sizes, int n_in,
                              void* d_out, int out_size) {
    const float* x     = (const float*)d_in[0];
    const int*   ei    = (const int*)d_in[1];
    const int*   batch = (const int*)d_in[2];
    const float* W1    = (const float*)d_in[3];
    const float* b1    = (const float*)d_in[4];
    const float* g1    = (const float*)d_in[5];
    const float* bt1   = (const float*)d_in[6];
    const float* W2    = (const float*)d_in[7];
    const float* b2    = (const float*)d_in[8];
    const float* g2    = (const float*)d_in[9];
    // d_in[10] (bt2) cancels analytically in BN2∘BN3
    const float* go    = (const float*)d_in[11];
    const float* bo    = (const float*)d_in[12];
    const float* fcW   = (const float*)d_in[13];
    const float* fcb   = (const float*)d_in[14];

    float* out  = (float*)d_out;
    float* Hout = out;
    float* Gout = out + (size_t)N_NODES * DIM;
    float* Cout = Gout + (size_t)N_GRAPHS * DIM;

    const int* src = ei;
    const int* dst = ei + N_EDGES;

    static bool attr_set = false;
    if (!attr_set) {
        cudaFuncSetAttribute(gemm_mma_kernel<1>, cudaFuncAttributeMaxDynamicSharedMemorySize, SMB_TOTAL);
        cudaFuncSetAttribute(gemm_mma_kernel<2>, cudaFuncAttributeMaxDynamicSharedMemorySize, SMB_TOTAL);
        attr_set = true;
    }

    const int nCopyBlocks    = (N_NODES * (DIM / 4)) / 256;      // 12500
    const int nScatterBlocks = (SCATTER_QTR + 255) / 256;        // 18750
    const int nGemmBlocks    = (N_NODES + 127) / 128;            // 782

    prep_kernel<<<(N_NODES + 256) / 256, 256>>>(W1, W2, batch);

    for (int i = 0; i < N_LAYERS; i++) {
        if (i == 0) {
            copy_to_agg_kernel<<<nCopyBlocks, 256>>>(x);
            scatter_add_kernel<false><<<nScatterBlocks, 256>>>(x, src, dst, 0,
                                                               nullptr, nullptr, nullptr);
        } else {
            copy_agg_relu_kernel<<<nCopyBlocks, 256>>>(i, g2 + (i - 1) * DIM,
                                                       go + (i - 1) * DIM, bo + (i - 1) * DIM);
            scatter_add_kernel<true><<<nScatterBlocks, 256>>>(nullptr, src, dst, i,
                                                              g2 + (i - 1) * DIM,
                                                              go + (i - 1) * DIM,
                                                              bo + (i - 1) * DIM);
        }
        gemm_mma_kernel<1><<<nGemmBlocks, 256, SMB_TOTAL>>>(i, i, b1 + i * DIM,
                                                            nullptr, nullptr);
        gemm_mma_kernel<2><<<nGemmBlocks, 256, SMB_TOTAL>>>(i + 3, i, b2 + i * DIM,
                                                            g1 + i * DIM, bt1 + i * DIM);
    }

    dim3 poolGrid(N_GRAPHS, 4);
    pool_transform_kernel<<<poolGrid, 128>>>(Hout, Gout, N_LAYERS - 1,
                                             g2 + (N_LAYERS - 1) * DIM,
                                             go + (N_LAYERS - 1) * DIM,
                                             bo + (N_LAYERS - 1) * DIM);
    fc_kernel<<<N_GRAPHS, 128>>>(Gout, fcW, fcb, Cout);
}